// round 3
// baseline (speedup 1.0000x reference)
#include <cuda_runtime.h>
#include <cuda_bf16.h>
#include <stdint.h>

#define NMAX 100000
#define EMAX 1000000
#define HID  64
#define NF   256
#define NCLS 40

// ---------------- scratch (device globals; no allocs allowed) ----------------
__device__ __align__(128) float g_dinv[NMAX];
__device__ __align__(128) int   g_count[NMAX];
__device__ __align__(128) int   g_scan[NMAX];
__device__ __align__(128) int   g_rowptr[NMAX + 1];
__device__ __align__(128) int   g_cursor[NMAX];
__device__ __align__(128) int   g_col[EMAX];
__device__ __align__(128) int   g_bsum[256];
__device__ __align__(128) int   g_boff[256];
__device__ __align__(128) float g_h[(size_t)NMAX * HID];     // h0
__device__ __align__(128) float g_hw[(size_t)NMAX * HID];    // h_prev @ W
__device__ __align__(128) float g_lcur[(size_t)NMAX * HID];  // current layer out
__device__ __align__(128) float g_lsum[(size_t)NMAX * HID];  // l1+l2+l3

// ---------------- degree / CSR build ----------------
__global__ void k_zero_count(int n) {
    int i = blockIdx.x * blockDim.x + threadIdx.x;
    if (i < n) g_count[i] = 0;
}

__global__ void k_count(const int* __restrict__ ei, int E) {
    int e = blockIdx.x * blockDim.x + threadIdx.x;
    if (e < E) {
        int d = ei[E + e];   // dst row
        atomicAdd(&g_count[d], 1);
    }
}

__global__ void k_dinv(int n) {
    int i = blockIdx.x * blockDim.x + threadIdx.x;
    if (i < n) g_dinv[i] = rsqrtf((float)(g_count[i] + 1));  // +1 self loop
}

// 3-kernel exclusive scan over g_count -> g_rowptr / g_cursor
__global__ void k_scan1(int n) {
    __shared__ int s[1024];
    int i = blockIdx.x * 1024 + threadIdx.x;
    int v = (i < n) ? g_count[i] : 0;
    s[threadIdx.x] = v;
    __syncthreads();
#pragma unroll
    for (int off = 1; off < 1024; off <<= 1) {
        int t = (threadIdx.x >= off) ? s[threadIdx.x - off] : 0;
        __syncthreads();
        s[threadIdx.x] += t;
        __syncthreads();
    }
    if (i < n) g_scan[i] = s[threadIdx.x];
    if (threadIdx.x == 1023) g_bsum[blockIdx.x] = s[1023];
}

__global__ void k_scan2(int nb) {
    if (threadIdx.x == 0 && blockIdx.x == 0) {
        int run = 0;
        for (int b = 0; b < nb; b++) { g_boff[b] = run; run += g_bsum[b]; }
    }
}

__global__ void k_scan3(int n) {
    int i = blockIdx.x * blockDim.x + threadIdx.x;
    if (i < n) {
        int incl = g_scan[i] + g_boff[i >> 10];
        g_rowptr[i + 1] = incl;
        g_cursor[i] = incl - g_count[i];
        if (i == 0) g_rowptr[0] = 0;
    }
}

__global__ void k_fill(const int* __restrict__ ei, int E) {
    int e = blockIdx.x * blockDim.x + threadIdx.x;
    if (e < E) {
        int s = ei[e];
        int d = ei[E + e];
        int pos = atomicAdd(&g_cursor[d], 1);
        g_col[pos] = s;
    }
}

// ---------------- GEMM 1: h0 = relu(x @ Wx + bx), 256 -> 64 ----------------
__global__ void k_gemm_x(const float* __restrict__ x,
                         const float* __restrict__ Wx,
                         const float* __restrict__ bx, int n) {
    __shared__ float Ws[(NF / 2) * HID];  // 32KB
    int node = blockIdx.x * blockDim.x + threadIdx.x;
    const float4* xr = (const float4*)(x + (size_t)node * NF);
    float4 acc[16];
#pragma unroll
    for (int j = 0; j < 16; j++) acc[j] = make_float4(0.f, 0.f, 0.f, 0.f);

#pragma unroll
    for (int half = 0; half < 2; half++) {
        __syncthreads();
        for (int i = threadIdx.x; i < (NF / 2) * HID; i += blockDim.x)
            Ws[i] = Wx[half * (NF / 2) * HID + i];
        __syncthreads();
        if (node < n) {
#pragma unroll 4
            for (int k4 = 0; k4 < NF / 8; k4++) {
                float4 xv = xr[half * (NF / 8) + k4];
#pragma unroll
                for (int c = 0; c < 4; c++) {
                    float xs = (c == 0) ? xv.x : (c == 1) ? xv.y : (c == 2) ? xv.z : xv.w;
                    const float4* wr = (const float4*)(Ws + (k4 * 4 + c) * HID);
#pragma unroll
                    for (int j = 0; j < 16; j++) {
                        float4 w = wr[j];
                        acc[j].x = fmaf(xs, w.x, acc[j].x);
                        acc[j].y = fmaf(xs, w.y, acc[j].y);
                        acc[j].z = fmaf(xs, w.z, acc[j].z);
                        acc[j].w = fmaf(xs, w.w, acc[j].w);
                    }
                }
            }
        }
    }
    if (node >= n) return;
    const float4* b4 = (const float4*)bx;
    float4* out = (float4*)(g_h + (size_t)node * HID);
#pragma unroll
    for (int j = 0; j < 16; j++) {
        float4 b = b4[j];
        float4 v;
        v.x = fmaxf(acc[j].x + b.x, 0.f);
        v.y = fmaxf(acc[j].y + b.y, 0.f);
        v.z = fmaxf(acc[j].z + b.z, 0.f);
        v.w = fmaxf(acc[j].w + b.w, 0.f);
        out[j] = v;
    }
}

// ---------------- GEMM: g_hw = hin @ W (64x64). sel: 0->g_h, 1->g_lcur ------
__global__ void k_gemm_h(const float* __restrict__ W, int sel, int n) {
    __shared__ float Ws[HID * HID];  // 16KB
    for (int i = threadIdx.x; i < HID * HID; i += blockDim.x) Ws[i] = W[i];
    __syncthreads();
    int node = blockIdx.x * blockDim.x + threadIdx.x;
    if (node >= n) return;
    const float* hin = sel ? g_lcur : g_h;
    const float4* hr = (const float4*)(hin + (size_t)node * HID);
    float4 acc[16];
#pragma unroll
    for (int j = 0; j < 16; j++) acc[j] = make_float4(0.f, 0.f, 0.f, 0.f);
#pragma unroll 4
    for (int k4 = 0; k4 < HID / 4; k4++) {
        float4 hv = hr[k4];
#pragma unroll
        for (int c = 0; c < 4; c++) {
            float xs = (c == 0) ? hv.x : (c == 1) ? hv.y : (c == 2) ? hv.z : hv.w;
            const float4* wr = (const float4*)(Ws + (k4 * 4 + c) * HID);
#pragma unroll
            for (int j = 0; j < 16; j++) {
                float4 w = wr[j];
                acc[j].x = fmaf(xs, w.x, acc[j].x);
                acc[j].y = fmaf(xs, w.y, acc[j].y);
                acc[j].z = fmaf(xs, w.z, acc[j].z);
                acc[j].w = fmaf(xs, w.w, acc[j].w);
            }
        }
    }
    float4* out = (float4*)(g_hw + (size_t)node * HID);
#pragma unroll
    for (int j = 0; j < 16; j++) out[j] = acc[j];
}

// ---------------- aggregation (one warp per node, float2 per lane) ----------
__global__ void k_agg(const float* __restrict__ bias, int accum, int n) {
    int gw = (blockIdx.x * blockDim.x + threadIdx.x) >> 5;
    int lane = threadIdx.x & 31;
    if (gw >= n) return;
    int v = gw;
    float dv = g_dinv[v];
    const float2* hw2 = (const float2*)g_hw;
    float2 hs = hw2[(size_t)v * 32 + lane];
    float sn = dv * dv;
    float2 acc;
    acc.x = hs.x * sn;
    acc.y = hs.y * sn;
    int beg = g_rowptr[v];
    int end = g_rowptr[v + 1];
    for (int e = beg; e < end; e++) {
        int u = g_col[e];
        float nrm = dv * g_dinv[u];
        float2 hv = hw2[(size_t)u * 32 + lane];
        acc.x = fmaf(nrm, hv.x, acc.x);
        acc.y = fmaf(nrm, hv.y, acc.y);
    }
    float2 b = ((const float2*)bias)[lane];
    acc.x += b.x;
    acc.y += b.y;
    ((float2*)g_lcur)[(size_t)v * 32 + lane] = acc;
    float2* ls = (float2*)g_lsum;
    if (accum) {
        float2 t = ls[(size_t)v * 32 + lane];
        t.x += acc.x;
        t.y += acc.y;
        ls[(size_t)v * 32 + lane] = t;
    } else {
        ls[(size_t)v * 32 + lane] = acc;
    }
}

// ---------------- final: out = relu((lsum/3) @ Wz + bz), 64 -> 40 -----------
__global__ void k_final(const float* __restrict__ Wz,
                        const float* __restrict__ bz,
                        float* __restrict__ out, int n) {
    __shared__ float Ws[HID * NCLS];  // 10.24KB
    for (int i = threadIdx.x; i < HID * NCLS; i += blockDim.x) Ws[i] = Wz[i];
    __syncthreads();
    int node = blockIdx.x * blockDim.x + threadIdx.x;
    if (node >= n) return;
    const float4* hr = (const float4*)(g_lsum + (size_t)node * HID);
    float4 acc[10];
#pragma unroll
    for (int j = 0; j < 10; j++) acc[j] = make_float4(0.f, 0.f, 0.f, 0.f);
#pragma unroll 4
    for (int k4 = 0; k4 < HID / 4; k4++) {
        float4 hv = hr[k4];
#pragma unroll
        for (int c = 0; c < 4; c++) {
            float xs = (c == 0) ? hv.x : (c == 1) ? hv.y : (c == 2) ? hv.z : hv.w;
            const float4* wr = (const float4*)(Ws + (k4 * 4 + c) * NCLS);
#pragma unroll
            for (int j = 0; j < 10; j++) {
                float4 w = wr[j];
                acc[j].x = fmaf(xs, w.x, acc[j].x);
                acc[j].y = fmaf(xs, w.y, acc[j].y);
                acc[j].z = fmaf(xs, w.z, acc[j].z);
                acc[j].w = fmaf(xs, w.w, acc[j].w);
            }
        }
    }
    const float THIRD = 1.f / 3.f;
    const float4* b4 = (const float4*)bz;
    float4* o = (float4*)(out + (size_t)node * NCLS);
#pragma unroll
    for (int j = 0; j < 10; j++) {
        float4 b = b4[j];
        float4 v;
        v.x = fmaxf(fmaf(acc[j].x, THIRD, b.x), 0.f);
        v.y = fmaxf(fmaf(acc[j].y, THIRD, b.y), 0.f);
        v.z = fmaxf(fmaf(acc[j].z, THIRD, b.z), 0.f);
        v.w = fmaxf(fmaf(acc[j].w, THIRD, b.w), 0.f);
        o[j] = v;
    }
}

// ---------------- launch (kernel launches ONLY) ----------------
extern "C" void kernel_launch(void* const* d_in, const int* in_sizes, int n_in,
                              void* d_out, int out_size) {
    const float* x  = (const float*)d_in[0];
    const int*   ei = (const int*)d_in[1];   // int32! (JAX default x64-disabled)
    const float* Wx = (const float*)d_in[2];
    const float* bx = (const float*)d_in[3];
    const float* W1 = (const float*)d_in[4];
    const float* b1 = (const float*)d_in[5];
    const float* W2 = (const float*)d_in[6];
    const float* b2 = (const float*)d_in[7];
    const float* W3 = (const float*)d_in[8];
    const float* b3 = (const float*)d_in[9];
    const float* Wz = (const float*)d_in[10];
    const float* bz = (const float*)d_in[11];
    float* out = (float*)d_out;

    int n = in_sizes[0] / NF;
    int E = in_sizes[1] / 2;

    int tb = 256;
    int nBlk = (n + tb - 1) / tb;
    int eBlk = (E + tb - 1) / tb;
    int scanBlocks = (n + 1023) / 1024;
    int aggBlk = (n + 7) / 8;  // 8 warps per block

    // CSR build
    k_zero_count<<<nBlk, tb>>>(n);
    k_count<<<eBlk, tb>>>(ei, E);
    k_dinv<<<nBlk, tb>>>(n);
    k_scan1<<<scanBlocks, 1024>>>(n);
    k_scan2<<<1, 32>>>(scanBlocks);
    k_scan3<<<nBlk, tb>>>(n);
    k_fill<<<eBlk, tb>>>(ei, E);

    // h0 = relu(x @ Wx + bx)
    k_gemm_x<<<nBlk, tb>>>(x, Wx, bx, n);

    // layer 1
    k_gemm_h<<<nBlk, tb>>>(W1, 0, n);
    k_agg<<<aggBlk, tb>>>(b1, 0, n);
    // layer 2
    k_gemm_h<<<nBlk, tb>>>(W2, 1, n);
    k_agg<<<aggBlk, tb>>>(b2, 1, n);
    // layer 3
    k_gemm_h<<<nBlk, tb>>>(W3, 1, n);
    k_agg<<<aggBlk, tb>>>(b3, 1, n);

    // out = relu((lsum/3) @ Wz + bz)
    k_final<<<nBlk, tb>>>(Wz, bz, out, n);
}